// round 1
// baseline (speedup 1.0000x reference)
#include <cuda_runtime.h>
#include <math.h>

#define BATCH   32
#define SEQ     4096
#define C_IN    7
#define NF      35          // 5 * C_IN feature channels
#define D_MODEL 512
#define WINDOW  24
#define KW      3
#define KDIM    (NF * KW)   // 105

// ---------------------------------------------------------------------------
// Scratch: feats stored transposed per batch: g_feats[b][i][s]
// ---------------------------------------------------------------------------
__device__ float g_feats[(size_t)BATCH * NF * SEQ];

// ---------------------------------------------------------------------------
// Phase 1: rolling stats.  One block handles 256 consecutive s for one batch.
// ---------------------------------------------------------------------------
#define P1_TS 256

__global__ __launch_bounds__(P1_TS) void stats_kernel(const float* __restrict__ x) {
    __shared__ float sx[(P1_TS + WINDOW - 1) * C_IN];   // 279*7 floats
    const int b   = blockIdx.y;
    const int s0  = blockIdx.x * P1_TS;
    const int tid = threadIdx.x;
    const float* xb = x + (size_t)b * SEQ * C_IN;

    // Load halo'd tile: local row l corresponds to global s = s0 - 23 + l,
    // clamped to 0 (reference pads by repeating x[:, :1, :]).
    for (int idx = tid; idx < (P1_TS + WINDOW - 1) * C_IN; idx += P1_TS) {
        int sg = s0 - (WINDOW - 1) + idx / C_IN;
        int c  = idx % C_IN;
        if (sg < 0) sg = 0;
        sx[idx] = xb[(size_t)sg * C_IN + c];
    }
    __syncthreads();

    const int s = s0 + tid;
    float* fb = g_feats + (size_t)b * NF * SEQ;

    #pragma unroll
    for (int c = 0; c < C_IN; c++) {
        float sum = 0.0f, mx = -3.0e38f, mn = 3.0e38f;
        #pragma unroll
        for (int t = 0; t < WINDOW; t++) {
            float v = sx[(tid + t) * C_IN + c];
            sum += v;
            mx = fmaxf(mx, v);
            mn = fminf(mn, v);
        }
        float mean = sum * (1.0f / WINDOW);
        float s2 = 0.0f;
        #pragma unroll
        for (int t = 0; t < WINDOW; t++) {
            float d = sx[(tid + t) * C_IN + c] - mean;
            s2 += d * d;
        }
        float sd = sqrtf(s2 * (1.0f / (WINDOW - 1)) + 1e-12f);
        float xv = sx[(tid + WINDOW - 1) * C_IN + c];   // window's last = x[s]

        fb[(size_t)(c)      * SEQ + s] = xv;
        fb[(size_t)(7 + c)  * SEQ + s] = mean;
        fb[(size_t)(14 + c) * SEQ + s] = mx;
        fb[(size_t)(21 + c) * SEQ + s] = mn;
        fb[(size_t)(28 + c) * SEQ + s] = sd;
    }
}

// ---------------------------------------------------------------------------
// Phase 2: y[b,s,d] = bias[d] + sum_{i,k} W[d,i,k] * feats[b, wrap(s-1+k), i]
// GEMM-style tiling: 128 (s) x 128 (d) per block, 256 threads, 8x8 microtile,
// packed f32x2 FMAs.
// ---------------------------------------------------------------------------
#define BM 128
#define BN 128
#define SF_LD (BM + 2 + 2)          // 132, keeps rows 16B-aligned
#define SMEM_W_FLOATS (KDIM * BN)   // 13440
#define SMEM_F_FLOATS (NF * SF_LD)  // 4620
#define SMEM_BYTES ((SMEM_W_FLOATS + SMEM_F_FLOATS) * 4)  // 72240

__global__ __launch_bounds__(256, 2) void conv_kernel(const float* __restrict__ Wg,
                                                      const float* __restrict__ bias,
                                                      float* __restrict__ out) {
    extern __shared__ float sm[];
    float* sW = sm;                       // [KDIM][BN]
    float* sF = sm + SMEM_W_FLOATS;       // [NF][SF_LD]

    const int s0 = blockIdx.x * BM;
    const int n0 = blockIdx.y * BN;
    const int b  = blockIdx.z;
    const int tid = threadIdx.x;
    const int tx = tid & 15;              // d group
    const int ty = tid >> 4;              // s group

    // Load W tile transposed: sW[kappa][dl] = W[(n0+dl)*105 + kappa].
    // Consecutive threads -> consecutive dl -> conflict-free smem writes;
    // gmem reads are strided but W is tiny and L2-resident.
    for (int idx = tid; idx < SMEM_W_FLOATS; idx += 256) {
        int dl = idx & (BN - 1);
        int kk = idx >> 7;                // BN == 128
        sW[kk * BN + dl] = Wg[(size_t)(n0 + dl) * KDIM + kk];
    }

    // Load feats halo: sF[i][t] = feats[b][i][(s0 - 1 + t) mod SEQ], t in [0,130)
    const float* fb = g_feats + (size_t)b * NF * SEQ;
    for (int idx = tid; idx < NF * (BM + 2); idx += 256) {
        int t = idx % (BM + 2);
        int i = idx / (BM + 2);
        int sg = (s0 - 1 + t) & (SEQ - 1);
        sF[i * SF_LD + t] = fb[(size_t)i * SEQ + sg];
    }
    __syncthreads();

    // Accumulators: 8 s-rows x 4 d-pairs, packed f32x2.
    unsigned long long acc[8][4];
    #pragma unroll
    for (int j = 0; j < 8; j++)
        #pragma unroll
        for (int p = 0; p < 4; p++)
            acc[j][p] = 0ULL;

    const int mbase = ty * 8;

    #pragma unroll 1
    for (int i = 0; i < NF; i++) {
        // 10 feats values cover the 3 shifted k-taps of this thread's 8 rows.
        // Pre-pack each value as {v, v} once (reused across k).
        unsigned long long pav[10];
        #pragma unroll
        for (int t = 0; t < 10; t++) {
            float v = sF[i * SF_LD + mbase + t];
            asm("mov.b64 %0, {%1, %1};" : "=l"(pav[t]) : "f"(v));
        }
        #pragma unroll
        for (int k = 0; k < KW; k++) {
            const int kk = i * KW + k;
            unsigned long long wv[4];
            #pragma unroll
            for (int p = 0; p < 4; p++)
                wv[p] = *(const unsigned long long*)&sW[kk * BN + 2 * tx + 32 * p];
            #pragma unroll
            for (int j = 0; j < 8; j++) {
                #pragma unroll
                for (int p = 0; p < 4; p++)
                    asm("fma.rn.f32x2 %0, %1, %2, %0;"
                        : "+l"(acc[j][p]) : "l"(pav[j + k]), "l"(wv[p]));
            }
        }
    }

    // Epilogue: bias + store.  Thread's d indices: n0 + 2*tx + 32*p (+0/+1).
    float2 bv[4];
    #pragma unroll
    for (int p = 0; p < 4; p++)
        bv[p] = *(const float2*)&bias[n0 + 2 * tx + 32 * p];

    #pragma unroll
    for (int j = 0; j < 8; j++) {
        const int s = s0 + mbase + j;
        float* orow = out + ((size_t)b * SEQ + s) * D_MODEL + n0;
        #pragma unroll
        for (int p = 0; p < 4; p++) {
            float lo, hi;
            asm("mov.b64 {%0, %1}, %2;" : "=f"(lo), "=f"(hi) : "l"(acc[j][p]));
            float2 o;
            o.x = lo + bv[p].x;
            o.y = hi + bv[p].y;
            *(float2*)&orow[2 * tx + 32 * p] = o;
        }
    }
}

// ---------------------------------------------------------------------------
// Launch
// ---------------------------------------------------------------------------
extern "C" void kernel_launch(void* const* d_in, const int* in_sizes, int n_in,
                              void* d_out, int out_size) {
    // Robust input identification by element count.
    const float* x    = nullptr;
    const float* Wg   = nullptr;
    const float* bias = nullptr;
    for (int i = 0; i < n_in; i++) {
        if (in_sizes[i] == BATCH * SEQ * C_IN)      x    = (const float*)d_in[i];
        else if (in_sizes[i] == D_MODEL * KDIM)     Wg   = (const float*)d_in[i];
        else if (in_sizes[i] == D_MODEL)            bias = (const float*)d_in[i];
        // BATCH*SEQ*4 == x_mark: unused by the reference math.
    }
    float* out = (float*)d_out;

    cudaFuncSetAttribute(conv_kernel, cudaFuncAttributeMaxDynamicSharedMemorySize,
                         SMEM_BYTES);

    dim3 g1(SEQ / P1_TS, BATCH);
    stats_kernel<<<g1, P1_TS>>>(x);

    dim3 g2(SEQ / BM, D_MODEL / BN, BATCH);
    conv_kernel<<<g2, 256, SMEM_BYTES>>>(Wg, bias, out);
}